// round 5
// baseline (speedup 1.0000x reference)
#include <cuda_runtime.h>
#include <cuda_bf16.h>
#include <math.h>

#define B_      8
#define NSNP    500000
#define NNODE   2000000
#define NG      20000
#define NF      8
#define H1      1024
#define H2      256
#define H3      16
#define BN_EPS  1e-5f

#define KSPLIT1 400
#define KCHUNK1 50     // 400 * 50 = 20000
#define JSPLIT1 2
#define KSPLIT2 32
#define KCHUNK2 32     // 32 * 32 = 1024

// ---------------- scratch ----------------------------------------------------
__device__ float g_scaled[NSNP * B_];            // [n][b]  16 MB
__device__ float g_sample[NG * B_];              // [g][b]  640 KB
__device__ float g_h1p[KSPLIT1 * B_ * H1];       // 13 MB partials
__device__ float g_h1s[B_ * H1];                 // summed (pre-BN)
__device__ float g_h2p[KSPLIT2 * B_ * H2];       // 256 KB partials
__device__ float g_h2[B_ * H2];                  // post BN+ReLU

// ---------------- K1: fused zero(g_sample, g_h1s) + scale --------------------
#define SCALE_BLOCKS ((NSNP / 4 + 255) / 256)                    // 489
#define NZERO        ((NG * B_ + B_ * H1) / 4)                   // 42048 float4
#define ZERO_BLOCKS  ((NZERO + 255) / 256)                       // 165
__global__ void k_prep(const float* __restrict__ snp,
                       const float* __restrict__ filters) {
    if (blockIdx.x >= SCALE_BLOCKS) {
        int i = (blockIdx.x - SCALE_BLOCKS) * blockDim.x + threadIdx.x;
        const int n0 = NG * B_ / 4;
        if (i < n0)
            reinterpret_cast<float4*>(g_sample)[i] =
                make_float4(0.f, 0.f, 0.f, 0.f);
        else if (i < NZERO)
            reinterpret_cast<float4*>(g_h1s)[i - n0] =
                make_float4(0.f, 0.f, 0.f, 0.f);
        return;
    }
    int q = blockIdx.x * blockDim.x + threadIdx.x;   // float4 index over n
    if (q >= NSNP / 4) return;
    float4 s = make_float4(0.f, 0.f, 0.f, 0.f);
#pragma unroll
    for (int f = 0; f < NF; f++) {
        float4 v = __ldg(reinterpret_cast<const float4*>(filters) +
                         (size_t)f * (NSNP / 4) + q);
        s.x += v.x; s.y += v.y; s.z += v.z; s.w += v.w;
    }
    const float inv = 1.0f / NF;
    s.x *= inv; s.y *= inv; s.z *= inv; s.w *= inv;

    float4 sv[NF];
#pragma unroll
    for (int b = 0; b < NF; b++)
        sv[b] = __ldg(reinterpret_cast<const float4*>(snp) +
                      (size_t)b * (NSNP / 4) + q);

    int n0 = q * 4;
    float4* o = reinterpret_cast<float4*>(g_scaled + (size_t)n0 * 8);
    o[0] = make_float4(sv[0].x * s.x, sv[1].x * s.x, sv[2].x * s.x, sv[3].x * s.x);
    o[1] = make_float4(sv[4].x * s.x, sv[5].x * s.x, sv[6].x * s.x, sv[7].x * s.x);
    o[2] = make_float4(sv[0].y * s.y, sv[1].y * s.y, sv[2].y * s.y, sv[3].y * s.y);
    o[3] = make_float4(sv[4].y * s.y, sv[5].y * s.y, sv[6].y * s.y, sv[7].y * s.y);
    o[4] = make_float4(sv[0].z * s.z, sv[1].z * s.z, sv[2].z * s.z, sv[3].z * s.z);
    o[5] = make_float4(sv[4].z * s.z, sv[5].z * s.z, sv[6].z * s.z, sv[7].z * s.z);
    o[6] = make_float4(sv[0].w * s.w, sv[1].w * s.w, sv[2].w * s.w, sv[3].w * s.w);
    o[7] = make_float4(sv[4].w * s.w, sv[5].w * s.w, sv[6].w * s.w, sv[7].w * s.w);
}

// ---------------- K2: shfl-free warp-cooperative segmented sum ---------------
#define NODES_PER_SUB 16
#define NODES_PER_WARP 64
__global__ void k_segsum(const int* __restrict__ ids,
                         const int* __restrict__ seg) {
    int gwarp = (blockIdx.x * blockDim.x + threadIdx.x) >> 5;
    int lane  = threadIdx.x & 31;
    int sub   = lane >> 3;
    int b     = lane & 7;
    long wbase = (long)gwarp * NODES_PER_WARP;
    if (wbase >= NNODE) return;
    long base = wbase + (long)sub * NODES_PER_SUB;

    const int4* ip = reinterpret_cast<const int4*>(ids + base);
    const int4* sp = reinterpret_cast<const int4*>(seg + base);
    int4 i0 = __ldg(ip),     i1 = __ldg(ip + 1);
    int4 i2 = __ldg(ip + 2), i3 = __ldg(ip + 3);
    int4 s0 = __ldg(sp),     s1 = __ldg(sp + 1);
    int4 s2 = __ldg(sp + 2), s3 = __ldg(sp + 3);
    int id[16] = {i0.x, i0.y, i0.z, i0.w, i1.x, i1.y, i1.z, i1.w,
                  i2.x, i2.y, i2.z, i2.w, i3.x, i3.y, i3.z, i3.w};
    int sg[16] = {s0.x, s0.y, s0.z, s0.w, s1.x, s1.y, s1.z, s1.w,
                  s2.x, s2.y, s2.z, s2.w, s3.x, s3.y, s3.z, s3.w};

    float v[16];
#pragma unroll
    for (int k = 0; k < 16; k++)
        v[k] = __ldg(g_scaled + (size_t)id[k] * 8 + b);

    int cur = sg[0];
    float acc = 0.f;
#pragma unroll
    for (int k = 0; k < 16; k++) {
        if (sg[k] != cur) {
            atomicAdd(&g_sample[(size_t)cur * 8 + b], acc);
            acc = 0.f;
            cur = sg[k];
        }
        acc += v[k];
    }
    atomicAdd(&g_sample[(size_t)cur * 8 + b], acc);
}

// ---------------- K3: GEMM1 partials (k-split x j-split) ---------------------
__global__ void k_gemm1(const float* __restrict__ W1) {
    __shared__ float ssamp[KCHUNK1][8];
    int bx  = blockIdx.x;
    int blk = bx >> 1;
    int jh  = bx & 1;
    int k0  = blk * KCHUNK1;
    int t   = threadIdx.x;

    if (t < KCHUNK1 * 2)
        reinterpret_cast<float4*>(ssamp)[t] =
            reinterpret_cast<const float4*>(g_sample)[k0 * 2 + t];
    __syncthreads();

    int j = jh * 512 + t * 2;
    float acc[8][2];
#pragma unroll
    for (int b = 0; b < 8; b++) { acc[b][0] = 0.f; acc[b][1] = 0.f; }

#pragma unroll 10
    for (int kk = 0; kk < KCHUNK1; kk++) {
        float2 w = __ldg(reinterpret_cast<const float2*>(
            W1 + (size_t)(k0 + kk) * H1 + j));
#pragma unroll
        for (int b = 0; b < 8; b++) {
            float sv = ssamp[kk][b];
            acc[b][0] = fmaf(sv, w.x, acc[b][0]);
            acc[b][1] = fmaf(sv, w.y, acc[b][1]);
        }
    }
    float* dst = g_h1p + (size_t)blk * (B_ * H1);
#pragma unroll
    for (int b = 0; b < 8; b++)
        *reinterpret_cast<float2*>(dst + b * H1 + j) =
            make_float2(acc[b][0], acc[b][1]);
}

// ---------------- K4: two-level reduce of h1 partials -> g_h1s (atomic) ------
// grid = 64 col-groups * 8 split-groups = 512 blocks, 256 threads.
// warp w covers splits {sg*50 + w, +8, ...}; lane = col4 within group (coalesced).
__global__ void k_reduce1() {
    __shared__ float4 sred[8][32];
    int cg   = blockIdx.x & 63;
    int sgp  = blockIdx.x >> 6;          // 0..7
    int lane = threadIdx.x & 31;
    int w    = threadIdx.x >> 5;
    int col4 = cg * 32 + lane;           // 0..2047
    const float4* P = reinterpret_cast<const float4*>(g_h1p);

    float4 acc = make_float4(0.f, 0.f, 0.f, 0.f);
    int sEnd = sgp * 50 + 50;
#pragma unroll 7
    for (int s = sgp * 50 + w; s < sEnd; s += 8) {
        float4 v = __ldg(P + (size_t)s * (B_ * H1 / 4) + col4);
        acc.x += v.x; acc.y += v.y; acc.z += v.z; acc.w += v.w;
    }
    sred[w][lane] = acc;
    __syncthreads();
    if (w == 0) {
        float4 tot = sred[0][lane];
#pragma unroll
        for (int x = 1; x < 8; x++) {
            float4 v = sred[x][lane];
            tot.x += v.x; tot.y += v.y; tot.z += v.z; tot.w += v.w;
        }
        float* dst = g_h1s + col4 * 4;
        atomicAdd(dst + 0, tot.x);
        atomicAdd(dst + 1, tot.y);
        atomicAdd(dst + 2, tot.z);
        atomicAdd(dst + 3, tot.w);
    }
}

// ---------------- K5: GEMM2 partials with fused BN1 + ReLU on load -----------
__global__ void k_gemm2(const float* __restrict__ W2,
                        const float* __restrict__ b1,
                        const float* __restrict__ g1,
                        const float* __restrict__ be1) {
    __shared__ float sh[KCHUNK2 * 8];   // [kk][b]
    int blk = blockIdx.x;
    int k0  = blk * KCHUNK2;
    int t   = threadIdx.x;
    {
        int k = k0 + (t >> 3);
        int b = t & 7;
        float sc = g1[k] * rsqrtf(1.0f + BN_EPS);
        float v  = (g_h1s[b * H1 + k] + b1[k]) * sc + be1[k];
        sh[t] = fmaxf(v, 0.f);
    }
    __syncthreads();

    int j = t;
    float acc[8];
#pragma unroll
    for (int b = 0; b < 8; b++) acc[b] = 0.f;
#pragma unroll 8
    for (int kk = 0; kk < KCHUNK2; kk++) {
        float w = __ldg(W2 + (size_t)(k0 + kk) * H2 + j);
#pragma unroll
        for (int b = 0; b < 8; b++)
            acc[b] = fmaf(sh[kk * 8 + b], w, acc[b]);
    }
    float* dst = g_h2p + (size_t)blk * (B_ * H2);
#pragma unroll
    for (int b = 0; b < 8; b++)
        dst[b * H2 + j] = acc[b];
}

// ---------------- K6: reduce h2 partials + BN + ReLU -------------------------
__global__ void k_reduce2(const float* __restrict__ b2,
                          const float* __restrict__ g2,
                          const float* __restrict__ be2) {
    int i = blockIdx.x * blockDim.x + threadIdx.x;
    if (i >= B_ * H2) return;
    float sum = 0.f;
#pragma unroll 8
    for (int s = 0; s < KSPLIT2; s++)
        sum += __ldg(g_h2p + (size_t)s * (B_ * H2) + i);
    int j = i & (H2 - 1);
    float sc = g2[j] * rsqrtf(1.0f + BN_EPS);
    g_h2[i] = fmaxf((sum + b2[j]) * sc + be2[j], 0.f);
}

// ---------------- K7: GEMM3 -> BN+ReLU -> head -> logits ---------------------
__global__ void k_final(const float* __restrict__ W3,
                        const float* __restrict__ b3,
                        const float* __restrict__ g3,
                        const float* __restrict__ be3,
                        const float* __restrict__ Wh1,
                        const float* __restrict__ bh1,
                        const float* __restrict__ gh,
                        const float* __restrict__ beh,
                        const float* __restrict__ Wh2,
                        const float* __restrict__ bh2,
                        float* __restrict__ out) {
    __shared__ float sh2[B_ * H2];
    __shared__ float sfeat[B_ * H3];
    int t = threadIdx.x;
    float sbn = rsqrtf(1.0f + BN_EPS);

    for (int i = t; i < B_ * H2; i += blockDim.x)
        sh2[i] = g_h2[i];
    __syncthreads();

    if (t < B_ * H3) {
        int b = t >> 4, j = t & 15;
        float acc = 0.f;
        for (int k = 0; k < H2; k++)
            acc = fmaf(sh2[b * H2 + k], W3[(size_t)k * H3 + j], acc);
        float v = (acc + b3[j]) * (g3[j] * sbn) + be3[j];
        sfeat[b * H3 + j] = fmaxf(v, 0.f);
    }
    __syncthreads();

    if (t < B_) {
        int b = t;
        float logit = bh2[0];
#pragma unroll
        for (int q = 0; q < 4; q++) {
            float acc = bh1[q];
            for (int p = 0; p < 15; p++)
                acc = fmaf(sfeat[b * H3 + p], Wh1[p * 4 + q], acc);
            float m = fmaxf(acc * (gh[q] * sbn) + beh[q], 0.f);
            logit = fmaf(m, Wh2[q], logit);
        }
        out[b] = logit;
    }
}

// ---------------- launch -----------------------------------------------------
extern "C" void kernel_launch(void* const* d_in, const int* in_sizes, int n_in,
                              void* d_out, int out_size) {
    const float* snp      = (const float*)d_in[0];
    const int*   snp_ids  = (const int*)  d_in[1];
    const int*   node_seg = (const int*)  d_in[2];
    const float* filters  = (const float*)d_in[3];
    const float* W1  = (const float*)d_in[4];
    const float* b1  = (const float*)d_in[5];
    const float* g1  = (const float*)d_in[6];
    const float* be1 = (const float*)d_in[7];
    const float* W2  = (const float*)d_in[8];
    const float* b2  = (const float*)d_in[9];
    const float* g2  = (const float*)d_in[10];
    const float* be2 = (const float*)d_in[11];
    const float* W3  = (const float*)d_in[12];
    const float* b3  = (const float*)d_in[13];
    const float* g3  = (const float*)d_in[14];
    const float* be3 = (const float*)d_in[15];
    const float* Wh1 = (const float*)d_in[16];
    const float* bh1 = (const float*)d_in[17];
    const float* gh  = (const float*)d_in[18];
    const float* beh = (const float*)d_in[19];
    const float* Wh2 = (const float*)d_in[20];
    const float* bh2 = (const float*)d_in[21];
    float* out = (float*)d_out;

    k_prep<<<SCALE_BLOCKS + ZERO_BLOCKS, 256>>>(snp, filters);
    int segsum_blocks = (NNODE / NODES_PER_WARP * 32 + 255) / 256;  // 3907
    k_segsum<<<segsum_blocks, 256>>>(snp_ids, node_seg);
    k_gemm1<<<KSPLIT1 * JSPLIT1, 256>>>(W1);
    k_reduce1<<<512, 256>>>();
    k_gemm2<<<KSPLIT2, 256>>>(W2, b1, g1, be1);
    k_reduce2<<<(B_ * H2 + 255) / 256, 256>>>(b2, g2, be2);
    k_final<<<1, 256>>>(W3, b3, g3, be3, Wh1, bh1, gh, beh, Wh2, bh2, out);
}

// round 6
// speedup vs baseline: 1.1007x; 1.1007x over previous
#include <cuda_runtime.h>
#include <cuda_bf16.h>
#include <math.h>

#define B_      8
#define NSNP    500000
#define NNODE   2000000
#define NG      20000
#define NF      8
#define H1      1024
#define H2      256
#define H3      16
#define BN_EPS  1e-5f

#define G1_KSPLIT 50
#define G1_KCHUNK 400     // 50 * 400 = 20000
#define KSPLIT2 32
#define KCHUNK2 32        // 32 * 32 = 1024

// ---------------- scratch ----------------------------------------------------
__device__ float g_scaled[NSNP * B_];            // [n][b]  16 MB
__device__ float g_sample[NG * B_];              // [g][b]  640 KB
__device__ float g_h1s[B_ * H1];                 // summed (pre-BN)
__device__ float g_h2p[KSPLIT2 * B_ * H2];       // 256 KB partials
__device__ float g_h2[B_ * H2];                  // post BN+ReLU

// ---------------- K1: fused zero(g_sample, g_h1s) + scale --------------------
#define SCALE_BLOCKS ((NSNP / 4 + 255) / 256)                    // 489
#define NZERO        ((NG * B_ + B_ * H1) / 4)                   // 42048 float4
#define ZERO_BLOCKS  ((NZERO + 255) / 256)                       // 165
__global__ void k_prep(const float* __restrict__ snp,
                       const float* __restrict__ filters) {
    if (blockIdx.x >= SCALE_BLOCKS) {
        int i = (blockIdx.x - SCALE_BLOCKS) * blockDim.x + threadIdx.x;
        const int n0 = NG * B_ / 4;
        if (i < n0)
            reinterpret_cast<float4*>(g_sample)[i] =
                make_float4(0.f, 0.f, 0.f, 0.f);
        else if (i < NZERO)
            reinterpret_cast<float4*>(g_h1s)[i - n0] =
                make_float4(0.f, 0.f, 0.f, 0.f);
        return;
    }
    int q = blockIdx.x * blockDim.x + threadIdx.x;   // float4 index over n
    if (q >= NSNP / 4) return;
    float4 s = make_float4(0.f, 0.f, 0.f, 0.f);
#pragma unroll
    for (int f = 0; f < NF; f++) {
        float4 v = __ldg(reinterpret_cast<const float4*>(filters) +
                         (size_t)f * (NSNP / 4) + q);
        s.x += v.x; s.y += v.y; s.z += v.z; s.w += v.w;
    }
    const float inv = 1.0f / NF;
    s.x *= inv; s.y *= inv; s.z *= inv; s.w *= inv;

    float4 sv[NF];
#pragma unroll
    for (int b = 0; b < NF; b++)
        sv[b] = __ldg(reinterpret_cast<const float4*>(snp) +
                      (size_t)b * (NSNP / 4) + q);

    int n0 = q * 4;
    float4* o = reinterpret_cast<float4*>(g_scaled + (size_t)n0 * 8);
    o[0] = make_float4(sv[0].x * s.x, sv[1].x * s.x, sv[2].x * s.x, sv[3].x * s.x);
    o[1] = make_float4(sv[4].x * s.x, sv[5].x * s.x, sv[6].x * s.x, sv[7].x * s.x);
    o[2] = make_float4(sv[0].y * s.y, sv[1].y * s.y, sv[2].y * s.y, sv[3].y * s.y);
    o[3] = make_float4(sv[4].y * s.y, sv[5].y * s.y, sv[6].y * s.y, sv[7].y * s.y);
    o[4] = make_float4(sv[0].z * s.z, sv[1].z * s.z, sv[2].z * s.z, sv[3].z * s.z);
    o[5] = make_float4(sv[4].z * s.z, sv[5].z * s.z, sv[6].z * s.z, sv[7].z * s.z);
    o[6] = make_float4(sv[0].w * s.w, sv[1].w * s.w, sv[2].w * s.w, sv[3].w * s.w);
    o[7] = make_float4(sv[4].w * s.w, sv[5].w * s.w, sv[6].w * s.w, sv[7].w * s.w);
}

// ---------------- K2: segmented sum, indices staged in shared ----------------
// Block covers 512 nodes (8 warps x 64). lane = sub*8 + b; subgroup handles
// 16 contiguous nodes; lane b owns batch b; gathers are 32B-coalesced.
#define SEG_NODES 512
__global__ void k_segsum(const int* __restrict__ ids,
                         const int* __restrict__ seg) {
    __shared__ int sids[SEG_NODES];
    __shared__ int sseg[SEG_NODES];
    int t = threadIdx.x;
    long blockBase = (long)blockIdx.x * SEG_NODES;
    long rem = NNODE - blockBase;                 // >= 64 always

    if (t < 128) {
        if (t * 4 < rem)
            reinterpret_cast<int4*>(sids)[t] =
                __ldg(reinterpret_cast<const int4*>(ids + blockBase) + t);
    } else {
        int u = t - 128;
        if (u * 4 < rem)
            reinterpret_cast<int4*>(sseg)[u] =
                __ldg(reinterpret_cast<const int4*>(seg + blockBase) + u);
    }
    __syncthreads();

    int w    = t >> 5;
    int lane = t & 31;
    int sub  = lane >> 3;
    int b    = lane & 7;
    int nb   = w * 64 + sub * 16;                 // node offset within block
    if (w * 64 >= rem) return;                    // whole-warp granular (64 | NNODE)

    // gather phase: 16 independent loads in flight
    float v[16];
#pragma unroll
    for (int k = 0; k < 16; k++)
        v[k] = __ldg(g_scaled + (size_t)sids[nb + k] * 8 + b);

    // accumulate phase with run-length flush
    int cur = sseg[nb];
    float acc = 0.f;
#pragma unroll
    for (int k = 0; k < 16; k++) {
        int sgk = sseg[nb + k];
        if (sgk != cur) {
            atomicAdd(&g_sample[(size_t)cur * 8 + b], acc);
            acc = 0.f;
            cur = sgk;
        }
        acc += v[k];
    }
    atomicAdd(&g_sample[(size_t)cur * 8 + b], acc);
}

// ---------------- K3: GEMM1 direct: g_h1s[b][j] += sum_k samp[k][b]*W1[k][j] --
// grid = 50 k-splits x 8 j-tiles(128 cols). 256 thr = 8 warps; warp w strides
// k rows {w, w+8, ...} (50 rows); lane owns 4 consecutive cols (LDG.128 of W).
__global__ void k_gemm1(const float* __restrict__ W1) {
    __shared__ float  ssamp[G1_KCHUNK][8];     // 12.8 KB
    __shared__ float4 sred[8][256];            // 32 KB
    int bx = blockIdx.x;
    int jt = bx & 7;
    int k0 = (bx >> 3) * G1_KCHUNK;
    int t  = threadIdx.x;
    int w  = t >> 5;
    int lane = t & 31;
    int j0 = jt * 128;

    // stage sample chunk: 400 rows x 8 floats = 800 float4
    for (int i = t; i < G1_KCHUNK * 2; i += 256)
        reinterpret_cast<float4*>(ssamp)[i] =
            __ldg(reinterpret_cast<const float4*>(g_sample) + k0 * 2 + i);
    __syncthreads();

    int j = j0 + lane * 4;
    float acc[8][4];
#pragma unroll
    for (int b = 0; b < 8; b++)
#pragma unroll
        for (int c = 0; c < 4; c++) acc[b][c] = 0.f;

#pragma unroll 5
    for (int r = 0; r < G1_KCHUNK / 8; r++) {
        int row = r * 8 + w;
        float4 wv = __ldg(reinterpret_cast<const float4*>(
            W1 + (size_t)(k0 + row) * H1 + j));
        float4 sa = *reinterpret_cast<const float4*>(&ssamp[row][0]);
        float4 sb = *reinterpret_cast<const float4*>(&ssamp[row][4]);
        float sv[8] = {sa.x, sa.y, sa.z, sa.w, sb.x, sb.y, sb.z, sb.w};
#pragma unroll
        for (int b = 0; b < 8; b++) {
            acc[b][0] = fmaf(sv[b], wv.x, acc[b][0]);
            acc[b][1] = fmaf(sv[b], wv.y, acc[b][1]);
            acc[b][2] = fmaf(sv[b], wv.z, acc[b][2]);
            acc[b][3] = fmaf(sv[b], wv.w, acc[b][3]);
        }
    }

    // cross-warp reduce via shared, then spread atomics into g_h1s
#pragma unroll
    for (int b = 0; b < 8; b++)
        sred[w][lane * 8 + b] =
            make_float4(acc[b][0], acc[b][1], acc[b][2], acc[b][3]);
    __syncthreads();

    int lane_o = t >> 3;          // 0..31 : col4 within tile
    int b_o    = t & 7;           // batch
    float4 tot = sred[0][lane_o * 8 + b_o];
#pragma unroll
    for (int x = 1; x < 8; x++) {
        float4 v = sred[x][lane_o * 8 + b_o];
        tot.x += v.x; tot.y += v.y; tot.z += v.z; tot.w += v.w;
    }
    float* dst = g_h1s + b_o * H1 + j0 + lane_o * 4;
    atomicAdd(dst + 0, tot.x);
    atomicAdd(dst + 1, tot.y);
    atomicAdd(dst + 2, tot.z);
    atomicAdd(dst + 3, tot.w);
}

// ---------------- K4: GEMM2 partials with fused BN1 + ReLU on load -----------
__global__ void k_gemm2(const float* __restrict__ W2,
                        const float* __restrict__ b1,
                        const float* __restrict__ g1,
                        const float* __restrict__ be1) {
    __shared__ float sh[KCHUNK2 * 8];   // [kk][b]
    int blk = blockIdx.x;
    int k0  = blk * KCHUNK2;
    int t   = threadIdx.x;
    {
        int k = k0 + (t >> 3);
        int b = t & 7;
        float sc = g1[k] * rsqrtf(1.0f + BN_EPS);
        float v  = (g_h1s[b * H1 + k] + b1[k]) * sc + be1[k];
        sh[t] = fmaxf(v, 0.f);
    }
    __syncthreads();

    int j = t;
    float acc[8];
#pragma unroll
    for (int b = 0; b < 8; b++) acc[b] = 0.f;
#pragma unroll 8
    for (int kk = 0; kk < KCHUNK2; kk++) {
        float w = __ldg(W2 + (size_t)(k0 + kk) * H2 + j);
#pragma unroll
        for (int b = 0; b < 8; b++)
            acc[b] = fmaf(sh[kk * 8 + b], w, acc[b]);
    }
    float* dst = g_h2p + (size_t)blk * (B_ * H2);
#pragma unroll
    for (int b = 0; b < 8; b++)
        dst[b * H2 + j] = acc[b];
}

// ---------------- K5: reduce h2 partials + BN + ReLU -------------------------
__global__ void k_reduce2(const float* __restrict__ b2,
                          const float* __restrict__ g2,
                          const float* __restrict__ be2) {
    int i = blockIdx.x * blockDim.x + threadIdx.x;
    if (i >= B_ * H2) return;
    float sum = 0.f;
#pragma unroll 8
    for (int s = 0; s < KSPLIT2; s++)
        sum += __ldg(g_h2p + (size_t)s * (B_ * H2) + i);
    int j = i & (H2 - 1);
    float sc = g2[j] * rsqrtf(1.0f + BN_EPS);
    g_h2[i] = fmaxf((sum + b2[j]) * sc + be2[j], 0.f);
}

// ---------------- K6: GEMM3 -> BN+ReLU -> head -> logits ---------------------
__global__ void k_final(const float* __restrict__ W3,
                        const float* __restrict__ b3,
                        const float* __restrict__ g3,
                        const float* __restrict__ be3,
                        const float* __restrict__ Wh1,
                        const float* __restrict__ bh1,
                        const float* __restrict__ gh,
                        const float* __restrict__ beh,
                        const float* __restrict__ Wh2,
                        const float* __restrict__ bh2,
                        float* __restrict__ out) {
    __shared__ float sh2[B_ * H2];
    __shared__ float sfeat[B_ * H3];
    int t = threadIdx.x;
    float sbn = rsqrtf(1.0f + BN_EPS);

    for (int i = t; i < B_ * H2; i += blockDim.x)
        sh2[i] = g_h2[i];
    __syncthreads();

    if (t < B_ * H3) {
        int b = t >> 4, j = t & 15;
        float acc = 0.f;
        for (int k = 0; k < H2; k++)
            acc = fmaf(sh2[b * H2 + k], W3[(size_t)k * H3 + j], acc);
        float v = (acc + b3[j]) * (g3[j] * sbn) + be3[j];
        sfeat[b * H3 + j] = fmaxf(v, 0.f);
    }
    __syncthreads();

    if (t < B_) {
        int b = t;
        float logit = bh2[0];
#pragma unroll
        for (int q = 0; q < 4; q++) {
            float acc = bh1[q];
            for (int p = 0; p < 15; p++)
                acc = fmaf(sfeat[b * H3 + p], Wh1[p * 4 + q], acc);
            float m = fmaxf(acc * (gh[q] * sbn) + beh[q], 0.f);
            logit = fmaf(m, Wh2[q], logit);
        }
        out[b] = logit;
    }
}

// ---------------- launch -----------------------------------------------------
extern "C" void kernel_launch(void* const* d_in, const int* in_sizes, int n_in,
                              void* d_out, int out_size) {
    const float* snp      = (const float*)d_in[0];
    const int*   snp_ids  = (const int*)  d_in[1];
    const int*   node_seg = (const int*)  d_in[2];
    const float* filters  = (const float*)d_in[3];
    const float* W1  = (const float*)d_in[4];
    const float* b1  = (const float*)d_in[5];
    const float* g1  = (const float*)d_in[6];
    const float* be1 = (const float*)d_in[7];
    const float* W2  = (const float*)d_in[8];
    const float* b2  = (const float*)d_in[9];
    const float* g2  = (const float*)d_in[10];
    const float* be2 = (const float*)d_in[11];
    const float* W3  = (const float*)d_in[12];
    const float* b3  = (const float*)d_in[13];
    const float* g3  = (const float*)d_in[14];
    const float* be3 = (const float*)d_in[15];
    const float* Wh1 = (const float*)d_in[16];
    const float* bh1 = (const float*)d_in[17];
    const float* gh  = (const float*)d_in[18];
    const float* beh = (const float*)d_in[19];
    const float* Wh2 = (const float*)d_in[20];
    const float* bh2 = (const float*)d_in[21];
    float* out = (float*)d_out;

    k_prep<<<SCALE_BLOCKS + ZERO_BLOCKS, 256>>>(snp, filters);
    int segsum_blocks = (int)((NNODE + SEG_NODES - 1) / SEG_NODES);  // 3907
    k_segsum<<<segsum_blocks, 256>>>(snp_ids, node_seg);
    k_gemm1<<<G1_KSPLIT * 8, 256>>>(W1);
    k_gemm2<<<KSPLIT2, 256>>>(W2, b1, g1, be1);
    k_reduce2<<<(B_ * H2 + 255) / 256, 256>>>(b2, g2, be2);
    k_final<<<1, 256>>>(W3, b3, g3, be3, Wh1, bh1, gh, beh, Wh2, bh2, out);
}

// round 7
// speedup vs baseline: 1.2661x; 1.1503x over previous
#include <cuda_runtime.h>
#include <cuda_bf16.h>
#include <math.h>

#define B_      8
#define NSNP    500000
#define NNODE   2000000
#define NG      20000
#define NF      8
#define H1      1024
#define H2      256
#define H3      16
#define BN_EPS  1e-5f

#define G1_KSPLIT 50
#define G1_KCHUNK 400     // 50 * 400 = 20000

// ---------------- scratch ----------------------------------------------------
__device__ float g_scaled[NSNP * B_];            // [n][b]  16 MB
__device__ float g_sample[NG * B_];              // [g][b]  640 KB
__device__ float g_h1s[B_ * H1];                 // summed (pre-BN)
__device__ float g_h2s[B_ * H2];                 // summed (pre-BN)

// ---------------- K1: fused zero(g_sample, g_h1s, g_h2s) + scale -------------
#define SCALE_BLOCKS ((NSNP / 4 + 255) / 256)                          // 489
#define NZERO        ((NG * B_ + B_ * H1 + B_ * H2) / 4)               // float4s
#define ZERO_BLOCKS  ((NZERO + 255) / 256)
__global__ void k_prep(const float* __restrict__ snp,
                       const float* __restrict__ filters) {
    if (blockIdx.x >= SCALE_BLOCKS) {
        int i = (blockIdx.x - SCALE_BLOCKS) * blockDim.x + threadIdx.x;
        const int n0 = NG * B_ / 4;
        const int n1 = n0 + B_ * H1 / 4;
        if (i < n0)
            reinterpret_cast<float4*>(g_sample)[i] =
                make_float4(0.f, 0.f, 0.f, 0.f);
        else if (i < n1)
            reinterpret_cast<float4*>(g_h1s)[i - n0] =
                make_float4(0.f, 0.f, 0.f, 0.f);
        else if (i < NZERO)
            reinterpret_cast<float4*>(g_h2s)[i - n1] =
                make_float4(0.f, 0.f, 0.f, 0.f);
        return;
    }
    int q = blockIdx.x * blockDim.x + threadIdx.x;   // float4 index over n
    if (q >= NSNP / 4) return;
    float4 s = make_float4(0.f, 0.f, 0.f, 0.f);
#pragma unroll
    for (int f = 0; f < NF; f++) {
        float4 v = __ldg(reinterpret_cast<const float4*>(filters) +
                         (size_t)f * (NSNP / 4) + q);
        s.x += v.x; s.y += v.y; s.z += v.z; s.w += v.w;
    }
    const float inv = 1.0f / NF;
    s.x *= inv; s.y *= inv; s.z *= inv; s.w *= inv;

    float4 sv[NF];
#pragma unroll
    for (int b = 0; b < NF; b++)
        sv[b] = __ldg(reinterpret_cast<const float4*>(snp) +
                      (size_t)b * (NSNP / 4) + q);

    int n0 = q * 4;
    float4* o = reinterpret_cast<float4*>(g_scaled + (size_t)n0 * 8);
    o[0] = make_float4(sv[0].x * s.x, sv[1].x * s.x, sv[2].x * s.x, sv[3].x * s.x);
    o[1] = make_float4(sv[4].x * s.x, sv[5].x * s.x, sv[6].x * s.x, sv[7].x * s.x);
    o[2] = make_float4(sv[0].y * s.y, sv[1].y * s.y, sv[2].y * s.y, sv[3].y * s.y);
    o[3] = make_float4(sv[4].y * s.y, sv[5].y * s.y, sv[6].y * s.y, sv[7].y * s.y);
    o[4] = make_float4(sv[0].z * s.z, sv[1].z * s.z, sv[2].z * s.z, sv[3].z * s.z);
    o[5] = make_float4(sv[4].z * s.z, sv[5].z * s.z, sv[6].z * s.z, sv[7].z * s.z);
    o[6] = make_float4(sv[0].w * s.w, sv[1].w * s.w, sv[2].w * s.w, sv[3].w * s.w);
    o[7] = make_float4(sv[4].w * s.w, sv[5].w * s.w, sv[6].w * s.w, sv[7].w * s.w);
}

// ---------------- K2: segmented sum, indices staged in shared ----------------
#define SEG_NODES 512
__global__ void k_segsum(const int* __restrict__ ids,
                         const int* __restrict__ seg) {
    __shared__ int sids[SEG_NODES];
    __shared__ int sseg[SEG_NODES];
    int t = threadIdx.x;
    long blockBase = (long)blockIdx.x * SEG_NODES;
    long rem = NNODE - blockBase;

    if (t < 128) {
        if (t * 4 < rem)
            reinterpret_cast<int4*>(sids)[t] =
                __ldg(reinterpret_cast<const int4*>(ids + blockBase) + t);
    } else {
        int u = t - 128;
        if (u * 4 < rem)
            reinterpret_cast<int4*>(sseg)[u] =
                __ldg(reinterpret_cast<const int4*>(seg + blockBase) + u);
    }
    __syncthreads();

    int w    = t >> 5;
    int lane = t & 31;
    int sub  = lane >> 3;
    int b    = lane & 7;
    int nb   = w * 64 + sub * 16;
    if (w * 64 >= rem) return;

    float v[16];
#pragma unroll
    for (int k = 0; k < 16; k++)
        v[k] = __ldg(g_scaled + (size_t)sids[nb + k] * 8 + b);

    int cur = sseg[nb];
    float acc = 0.f;
#pragma unroll
    for (int k = 0; k < 16; k++) {
        int sgk = sseg[nb + k];
        if (sgk != cur) {
            atomicAdd(&g_sample[(size_t)cur * 8 + b], acc);
            acc = 0.f;
            cur = sgk;
        }
        acc += v[k];
    }
    atomicAdd(&g_sample[(size_t)cur * 8 + b], acc);
}

// ---------------- K3: GEMM1 direct: g_h1s[b][j] += sum_k samp[k][b]*W1[k][j] --
__global__ void k_gemm1(const float* __restrict__ W1) {
    __shared__ float  ssamp[G1_KCHUNK][8];     // 12.8 KB
    __shared__ float4 sred[8][256];            // 32 KB
    int bx = blockIdx.x;
    int jt = bx & 7;
    int k0 = (bx >> 3) * G1_KCHUNK;
    int t  = threadIdx.x;
    int w  = t >> 5;
    int lane = t & 31;
    int j0 = jt * 128;

    for (int i = t; i < G1_KCHUNK * 2; i += 256)
        reinterpret_cast<float4*>(ssamp)[i] =
            __ldg(reinterpret_cast<const float4*>(g_sample) + k0 * 2 + i);
    __syncthreads();

    int j = j0 + lane * 4;
    float acc[8][4];
#pragma unroll
    for (int b = 0; b < 8; b++)
#pragma unroll
        for (int c = 0; c < 4; c++) acc[b][c] = 0.f;

#pragma unroll 5
    for (int r = 0; r < G1_KCHUNK / 8; r++) {
        int row = r * 8 + w;
        float4 wv = __ldg(reinterpret_cast<const float4*>(
            W1 + (size_t)(k0 + row) * H1 + j));
        float4 sa = *reinterpret_cast<const float4*>(&ssamp[row][0]);
        float4 sb = *reinterpret_cast<const float4*>(&ssamp[row][4]);
        float sv[8] = {sa.x, sa.y, sa.z, sa.w, sb.x, sb.y, sb.z, sb.w};
#pragma unroll
        for (int b = 0; b < 8; b++) {
            acc[b][0] = fmaf(sv[b], wv.x, acc[b][0]);
            acc[b][1] = fmaf(sv[b], wv.y, acc[b][1]);
            acc[b][2] = fmaf(sv[b], wv.z, acc[b][2]);
            acc[b][3] = fmaf(sv[b], wv.w, acc[b][3]);
        }
    }

#pragma unroll
    for (int b = 0; b < 8; b++)
        sred[w][lane * 8 + b] =
            make_float4(acc[b][0], acc[b][1], acc[b][2], acc[b][3]);
    __syncthreads();

    int lane_o = t >> 3;
    int b_o    = t & 7;
    float4 tot = sred[0][lane_o * 8 + b_o];
#pragma unroll
    for (int x = 1; x < 8; x++) {
        float4 v = sred[x][lane_o * 8 + b_o];
        tot.x += v.x; tot.y += v.y; tot.z += v.z; tot.w += v.w;
    }
    float* dst = g_h1s + b_o * H1 + j0 + lane_o * 4;
    atomicAdd(dst + 0, tot.x);
    atomicAdd(dst + 1, tot.y);
    atomicAdd(dst + 2, tot.z);
    atomicAdd(dst + 3, tot.w);
}

// ---------------- K4: GEMM2 direct with fused BN1+ReLU on load ---------------
// grid = 32 ksplits x 8 jsplits = 256 blocks. Block: k0..k0+32, j0..j0+32.
// warp w handles 4 k-rows; lane = column. Spread atomics into g_h2s.
__global__ void k_gemm2(const float* __restrict__ W2,
                        const float* __restrict__ b1,
                        const float* __restrict__ g1,
                        const float* __restrict__ be1) {
    __shared__ float sh[32][8];         // BN1(h1) for this k-chunk
    __shared__ float sred[8][32 * 8];   // per-warp partials
    int bx = blockIdx.x;
    int js = bx & 7;
    int ks = bx >> 3;
    int k0 = ks * 32;
    int j0 = js * 32;
    int t  = threadIdx.x;
    int w  = t >> 5;
    int lane = t & 31;

    {
        int k = k0 + (t >> 3);
        int b = t & 7;
        float sc = g1[k] * rsqrtf(1.0f + BN_EPS);
        float v  = (g_h1s[b * H1 + k] + b1[k]) * sc + be1[k];
        sh[t >> 3][b] = fmaxf(v, 0.f);
    }
    __syncthreads();

    float acc[8];
#pragma unroll
    for (int b = 0; b < 8; b++) acc[b] = 0.f;
#pragma unroll
    for (int r = 0; r < 4; r++) {
        int row = w * 4 + r;
        float wv = __ldg(W2 + (size_t)(k0 + row) * H2 + j0 + lane);
#pragma unroll
        for (int b = 0; b < 8; b++)
            acc[b] = fmaf(sh[row][b], wv, acc[b]);
    }
#pragma unroll
    for (int b = 0; b < 8; b++)
        sred[w][lane * 8 + b] = acc[b];
    __syncthreads();

    int lane_o = t >> 3;    // column within j-tile
    int b_o    = t & 7;
    float tot = sred[0][lane_o * 8 + b_o];
#pragma unroll
    for (int x = 1; x < 8; x++)
        tot += sred[x][lane_o * 8 + b_o];
    atomicAdd(&g_h2s[b_o * H2 + j0 + lane_o], tot);
}

// ---------------- K5: BN2+ReLU -> GEMM3 -> BN+ReLU -> head -> logits ---------
__global__ void k_final(const float* __restrict__ b2,
                        const float* __restrict__ g2,
                        const float* __restrict__ be2,
                        const float* __restrict__ W3,
                        const float* __restrict__ b3,
                        const float* __restrict__ g3,
                        const float* __restrict__ be3,
                        const float* __restrict__ Wh1,
                        const float* __restrict__ bh1,
                        const float* __restrict__ gh,
                        const float* __restrict__ beh,
                        const float* __restrict__ Wh2,
                        const float* __restrict__ bh2,
                        float* __restrict__ out) {
    __shared__ float sh2[B_ * H2];
    __shared__ float spart[2][B_ * H3];
    __shared__ float sfeat[B_ * H3];
    int t = threadIdx.x;
    float sbn = rsqrtf(1.0f + BN_EPS);

    // Stage A: BN2 + ReLU from summed h2
    for (int i = t; i < B_ * H2; i += blockDim.x) {
        int j = i & (H2 - 1);
        float v = (g_h2s[i] + b2[j]) * (g2[j] * sbn) + be2[j];
        sh2[i] = fmaxf(v, 0.f);
    }
    __syncthreads();

    // Stage B: 2-way k-split GEMM3
    {
        int pair = t & 127;
        int half = t >> 7;
        int b = pair >> 4, j = pair & 15;
        float acc = 0.f;
        int kk0 = half * (H2 / 2);
        for (int k = kk0; k < kk0 + H2 / 2; k++)
            acc = fmaf(sh2[b * H2 + k], W3[(size_t)k * H3 + j], acc);
        spart[half][pair] = acc;
    }
    __syncthreads();
    if (t < B_ * H3) {
        int j = t & 15;
        float acc = spart[0][t] + spart[1][t];
        float v = (acc + b3[j]) * (g3[j] * sbn) + be3[j];
        sfeat[t] = fmaxf(v, 0.f);
    }
    __syncthreads();

    // Stage C: head
    if (t < B_) {
        int b = t;
        float logit = bh2[0];
#pragma unroll
        for (int q = 0; q < 4; q++) {
            float acc = bh1[q];
            for (int p = 0; p < 15; p++)
                acc = fmaf(sfeat[b * H3 + p], Wh1[p * 4 + q], acc);
            float m = fmaxf(acc * (gh[q] * sbn) + beh[q], 0.f);
            logit = fmaf(m, Wh2[q], logit);
        }
        out[b] = logit;
    }
}

// ---------------- launch -----------------------------------------------------
extern "C" void kernel_launch(void* const* d_in, const int* in_sizes, int n_in,
                              void* d_out, int out_size) {
    const float* snp      = (const float*)d_in[0];
    const int*   snp_ids  = (const int*)  d_in[1];
    const int*   node_seg = (const int*)  d_in[2];
    const float* filters  = (const float*)d_in[3];
    const float* W1  = (const float*)d_in[4];
    const float* b1  = (const float*)d_in[5];
    const float* g1  = (const float*)d_in[6];
    const float* be1 = (const float*)d_in[7];
    const float* W2  = (const float*)d_in[8];
    const float* b2  = (const float*)d_in[9];
    const float* g2  = (const float*)d_in[10];
    const float* be2 = (const float*)d_in[11];
    const float* W3  = (const float*)d_in[12];
    const float* b3  = (const float*)d_in[13];
    const float* g3  = (const float*)d_in[14];
    const float* be3 = (const float*)d_in[15];
    const float* Wh1 = (const float*)d_in[16];
    const float* bh1 = (const float*)d_in[17];
    const float* gh  = (const float*)d_in[18];
    const float* beh = (const float*)d_in[19];
    const float* Wh2 = (const float*)d_in[20];
    const float* bh2 = (const float*)d_in[21];
    float* out = (float*)d_out;

    k_prep<<<SCALE_BLOCKS + ZERO_BLOCKS, 256>>>(snp, filters);
    int segsum_blocks = (int)((NNODE + SEG_NODES - 1) / SEG_NODES);  // 3907
    k_segsum<<<segsum_blocks, 256>>>(snp_ids, node_seg);
    k_gemm1<<<G1_KSPLIT * 8, 256>>>(W1);
    k_gemm2<<<256, 256>>>(W2, b1, g1, be1);
    k_final<<<1, 256>>>(b2, g2, be2, W3, b3, g3, be3,
                        Wh1, bh1, gh, beh, Wh2, bh2, out);
}